// round 2
// baseline (speedup 1.0000x reference)
#include <cuda_runtime.h>
#include <math.h>

// GradientHistLoss — single persistent kernel with manual grid sync.
// Phases: zero-init | top-11-bit hist of gt | scan | collect candidates |
//         21-bit radix select on candidates (exact quantile) |
//         soft histograms (pred+gt) | finalize.

#define NBINS    64
#define BATCH    4
#define NBLOCKS  148          // <= SM count, one wave, co-resident => safe spin barrier
#define NTHREADS 256
#define SBLKS    (NBLOCKS / BATCH)   // 37 blocks per sample
#define RB0      2048         // top 11 bits
#define RB1      2048         // mid 11 bits
#define RB2      1024         // low 10 bits
#define CAND_CAP 294912       // worst case: every element in one bin

// ---- device scratch (static, no allocations) ----
__device__ unsigned g_hist[BATCH][RB0];
__device__ unsigned g_bin[BATCH][2];
__device__ unsigned g_rem[BATCH][2];
__device__ unsigned g_cand[BATCH][2][CAND_CAP];
__device__ unsigned g_ccnt[BATCH][2];
__device__ float    g_soft[BATCH][2][NBINS];
__device__ float    g_invbw[BATCH];

__device__ unsigned          g_bar_count;
__device__ volatile unsigned g_bar_gen;

// -------------------------------------------------------------------------
__device__ __forceinline__ void grid_sync() {
    __syncthreads();
    if (threadIdx.x == 0) {
        __threadfence();
        unsigned gen = g_bar_gen;
        unsigned arr = atomicAdd(&g_bar_count, 1u);
        if (arr == NBLOCKS - 1) {
            g_bar_count = 0u;
            __threadfence();
            g_bar_gen = gen + 1u;
        } else {
            while (g_bar_gen == gen) { __nanosleep(64); }
        }
        __threadfence();
    }
    __syncthreads();
}

// Locate ranks r0, r1 within `cnt[0..bins)` (block-collective, 256 threads).
// Writes {bin,rem} pairs into s_loc[0..3] (only matching thread writes each).
__device__ void locate2(const unsigned* cnt, int bins, unsigned r0, unsigned r1,
                        unsigned* s_scan, unsigned* s_loc) {
    int tid = threadIdx.x;
    int per = bins / NTHREADS;            // 8 or 4
    unsigned base = tid * per, sum = 0u;
    #pragma unroll 4
    for (int i = 0; i < per; i++) sum += cnt[base + i];
    s_scan[tid] = sum;
    __syncthreads();
    for (int o = 1; o < NTHREADS; o <<= 1) {      // inclusive Hillis-Steele scan
        unsigned t = (tid >= o) ? s_scan[tid - o] : 0u;
        __syncthreads();
        s_scan[tid] += t;
        __syncthreads();
    }
    unsigned incl = s_scan[tid], excl = incl - sum;
    unsigned rs[2] = {r0, r1};
    #pragma unroll
    for (int j = 0; j < 2; j++) {
        unsigned r = rs[j];
        if (excl <= r && r < incl) {
            unsigned local = r - excl;
            unsigned d = base;
            for (;;) { unsigned c = cnt[d]; if (local < c) break; local -= c; d++; }
            s_loc[2 * j] = d;
            s_loc[2 * j + 1] = local;
        }
    }
    __syncthreads();
}

__device__ float block_sum256(float v, float* red) {
    int tid = threadIdx.x;
    red[tid] = v;
    __syncthreads();
    #pragma unroll
    for (int s = 128; s >= 1; s >>= 1) {
        if (tid < s) red[tid] += red[tid + s];
        __syncthreads();
    }
    float r = red[0];
    __syncthreads();
    return r;
}

// -------------------------------------------------------------------------
__global__ void __launch_bounds__(NTHREADS, 1)
ghl_kernel(const float* __restrict__ pred, const float* __restrict__ gt,
           int nper, unsigned k, float frac, float* __restrict__ out) {
    __shared__ unsigned sh[RB0];        // 8KB: hists; reused as floats later
    __shared__ unsigned s_scan[NTHREADS];
    __shared__ unsigned s_loc[4];

    int tid  = threadIdx.x;
    int bx   = blockIdx.x;
    int samp = bx & 3;
    int sblk = bx >> 2;                 // 0..SBLKS-1
    const float* gb = gt + (size_t)samp * nper;

    // ---- phase 0: zero global state ----
    for (int i = bx * NTHREADS + tid; i < BATCH * RB0; i += NBLOCKS * NTHREADS)
        ((unsigned*)g_hist)[i] = 0u;
    if (bx == 0) {
        if (tid < BATCH * 2) ((unsigned*)g_ccnt)[tid] = 0u;
        for (int i = tid; i < BATCH * 2 * NBINS; i += NTHREADS)
            ((float*)g_soft)[i] = 0.0f;
    }
    grid_sync();

    // ---- phase 1: top-11-bit histogram of gt (one hist per sample) ----
    for (int i = tid; i < RB0; i += NTHREADS) sh[i] = 0u;
    __syncthreads();
    for (int i = sblk * NTHREADS + tid; i < nper; i += SBLKS * NTHREADS) {
        unsigned key = __float_as_uint(gb[i]);
        atomicAdd(&sh[key >> 21], 1u);
    }
    __syncthreads();
    for (int i = tid; i < RB0; i += NTHREADS) {
        unsigned v = sh[i];
        if (v) atomicAdd(&g_hist[samp][i], v);
    }
    grid_sync();

    // ---- phase 2: scan — find bins containing ranks k, k+1 ----
    if (bx < BATCH) {
        locate2(g_hist[bx], RB0, k, k + 1u, s_scan, s_loc);
        if (tid == 0) {
            g_bin[bx][0] = s_loc[0]; g_rem[bx][0] = s_loc[1];
            g_bin[bx][1] = s_loc[2]; g_rem[bx][1] = s_loc[3];
        }
    }
    grid_sync();

    // ---- phase 3: collect candidates in the target bins (L2-hot re-read) ----
    {
        unsigned b0 = g_bin[samp][0], b1 = g_bin[samp][1];
        for (int i = sblk * NTHREADS + tid; i < nper; i += SBLKS * NTHREADS) {
            unsigned key = __float_as_uint(gb[i]);
            unsigned t = key >> 21;
            if (t == b0) {
                unsigned s = atomicAdd(&g_ccnt[samp][0], 1u);
                if (s < CAND_CAP) g_cand[samp][0][s] = key;
            } else if (t == b1) {
                unsigned s = atomicAdd(&g_ccnt[samp][1], 1u);
                if (s < CAND_CAP) g_cand[samp][1][s] = key;
            }
        }
    }
    grid_sync();

    // ---- phase 4: radix select within candidates (blocks 0..3) ----
    if (bx < BATCH) {
        int b = bx;
        unsigned b0 = g_bin[b][0], b1 = g_bin[b][1];
        unsigned bufIdx[2], rIn[2], topbin[2];
        if (b1 == b0) {
            bufIdx[0] = 0; bufIdx[1] = 0;
            rIn[0] = g_rem[b][0]; rIn[1] = g_rem[b][0] + 1u;
            topbin[0] = b0; topbin[1] = b0;
        } else {
            bufIdx[0] = 0; bufIdx[1] = 1;
            rIn[0] = g_rem[b][0]; rIn[1] = g_rem[b][1];
            topbin[0] = b0; topbin[1] = b1;
        }
        float vals[2];
        for (int r = 0; r < 2; r++) {
            const unsigned* buf = g_cand[b][bufIdx[r]];
            unsigned c = g_ccnt[b][bufIdx[r]];
            // level A: bits [20:10]
            for (int i = tid; i < RB1; i += NTHREADS) sh[i] = 0u;
            __syncthreads();
            for (unsigned i = tid; i < c; i += NTHREADS)
                atomicAdd(&sh[(buf[i] >> 10) & 0x7FFu], 1u);
            __syncthreads();
            locate2(sh, RB1, rIn[r], 0xFFFFFFFFu, s_scan, s_loc);
            unsigned sa = s_loc[0], ra = s_loc[1];
            __syncthreads();
            // level B: bits [9:0] among candidates matching sa
            for (int i = tid; i < RB2; i += NTHREADS) sh[i] = 0u;
            __syncthreads();
            for (unsigned i = tid; i < c; i += NTHREADS) {
                unsigned kk = buf[i];
                if (((kk >> 10) & 0x7FFu) == sa) atomicAdd(&sh[kk & 0x3FFu], 1u);
            }
            __syncthreads();
            locate2(sh, RB2, ra, 0xFFFFFFFFu, s_scan, s_loc);
            unsigned sb2 = s_loc[0];
            vals[r] = __uint_as_float((topbin[r] << 21) | (sa << 10) | sb2);
            __syncthreads();
        }
        if (tid == 0) {
            float mv = vals[0] + frac * (vals[1] - vals[0]);
            g_invbw[b] = (mv > 0.0f) ? (float)NBINS / mv : 0.0f;
        }
    }
    grid_sync();

    // ---- phase 5: triangular soft histograms (pred + gt) ----
    {
        float* shf = (float*)sh;
        for (int i = tid; i < 2 * NBINS; i += NTHREADS) shf[i] = 0.0f;
        __syncthreads();
        float invbw = g_invbw[samp];
        const float* pb = pred + (size_t)samp * nper;
        for (int i = sblk * NTHREADS + tid; i < nper; i += SBLKS * NTHREADS) {
            float up = pb[i] * invbw;
            int   jp = (int)floorf(up);
            float fp = up - (float)jp;
            if (jp >= 0 && jp < NBINS) {
                atomicAdd(&shf[jp], 1.0f - fp);
                if (jp + 1 < NBINS) atomicAdd(&shf[jp + 1], fp);
            }
            float ug = gb[i] * invbw;
            int   jg = (int)floorf(ug);
            float fg = ug - (float)jg;
            if (jg >= 0 && jg < NBINS) {
                atomicAdd(&shf[NBINS + jg], 1.0f - fg);
                if (jg + 1 < NBINS) atomicAdd(&shf[NBINS + jg + 1], fg);
            }
        }
        __syncthreads();
        for (int i = tid; i < 2 * NBINS; i += NTHREADS) {
            float v = shf[i];
            if (v != 0.0f) atomicAdd(&((float*)g_soft)[samp * 2 * NBINS + i], v);
        }
    }
    grid_sync();

    // ---- phase 6: finalize (block 0) ----
    if (bx == 0) {
        float* red = (float*)s_scan;
        float total = 0.0f;
        float bwj = (tid < NBINS) ? expf(0.4f * (float)tid / (float)NBINS) : 0.0f;
        #pragma unroll
        for (int b = 0; b < BATCH; b++) {
            float p = (tid < NBINS) ? g_soft[b][0][tid] : 0.0f;
            float g = (tid < NBINS) ? g_soft[b][1][tid] : 0.0f;
            float sp = block_sum256(p, red);
            float sg = block_sum256(g, red);
            float diff = (tid < NBINS) ? fabsf(p / sp - g / sg) * bwj : 0.0f;
            float s = block_sum256(diff, red);
            total += s * (1.0f / (float)NBINS);
        }
        if (tid == 0) out[0] = total * (1.0f / (float)BATCH);
    }
}

// -------------------------------------------------------------------------
extern "C" void kernel_launch(void* const* d_in, const int* in_sizes, int n_in,
                              void* d_out, int out_size) {
    const float* pred = (const float*)d_in[0];
    const float* gt   = (const float*)d_in[1];
    int ntot = in_sizes[0];
    int nper = ntot / BATCH;

    double pos = 0.95 * (double)(nper - 1);
    unsigned k = (unsigned)pos;
    float frac = (float)(pos - (double)k);

    ghl_kernel<<<NBLOCKS, NTHREADS>>>(pred, gt, nper, k, frac, (float*)d_out);
}